// round 8
// baseline (speedup 1.0000x reference)
#include <cuda_runtime.h>

// DenseCRFLoss on GB300 — R4: s0+s1=1 identity, 512 threads (16 warps/SM),
// fused single-kernel finalize via counter-based last-block reduction.
//
// loss = -(1/N) * sum_{n,k,p,q} S[n,k,p] * exp(-0.5*||f_p - f_q||^2) * S[n,k,q]
// out  = WEIGHT * loss, WEIGHT = 2e-9, N = 4.
// Exponent in log2 units: K_pq = exp2( f'_p . f'_q + h'_p + h'_q ).
// Symmetry: total = sum(diag tiles) + 2*sum(strict-upper tiles).
// Class identity (s0+s1=1): w = s0q*(2*s0p-1) + (1-s0p).

#define N_IMG   4
#define P       4096
#define TS      512             // square tile size
#define NT      8               // P / TS
#define NTRI    36              // upper-tri tiles
#define NBLOCKS (N_IMG * NTRI)  // 144
#define THREADS 512

typedef unsigned long long u64;

__device__ float g_partial[NBLOCKS];
__device__ unsigned int g_count;   // zero-initialized; reset by last block each run

__device__ __forceinline__ float ex2f(float x) {
    float r; asm("ex2.approx.f32 %0, %1;" : "=f"(r) : "f"(x)); return r;
}
__device__ __forceinline__ u64 fma2(u64 a, u64 b, u64 c) {
    u64 d; asm("fma.rn.f32x2 %0, %1, %2, %3;" : "=l"(d) : "l"(a), "l"(b), "l"(c)); return d;
}
__device__ __forceinline__ u64 add2(u64 a, u64 b) {
    u64 d; asm("add.rn.f32x2 %0, %1, %2;" : "=l"(d) : "l"(a), "l"(b)); return d;
}
__device__ __forceinline__ u64 pack2(float lo, float hi) {
    u64 d; asm("mov.b64 %0, {%1, %2};" : "=l"(d) : "f"(lo), "f"(hi)); return d;
}
__device__ __forceinline__ float2 unpack2(u64 v) {
    float2 r; asm("mov.b64 {%0, %1}, %2;" : "=f"(r.x), "=f"(r.y) : "l"(v)); return r;
}

// Feature record: f[0..4] = feature * sqrt(log2e), f[5] = -0.5*log2e*|f|^2, f[6] = s0.
__device__ __forceinline__ void feat(const float* __restrict__ img,
                                     const float* __restrict__ seg,
                                     int n, int pix, float f[7]) {
    const float LOG2E = 1.44269504088896340736f;
    const float SQ    = 1.20112240878644981f;   // sqrt(LOG2E)
    int y = pix >> 6, x = pix & 63;
    int o = (2 * y) * 128 + 2 * x;

    const float* ib = img + (size_t)n * 3 * 16384;
    float r = ib[o];
    float g = ib[16384 + o];
    float b = ib[32768 + o];

    float f0 = (float)x * (1.0f / 50.0f);   // SIGMA_XY * SCALE = 50
    float f1 = (float)y * (1.0f / 50.0f);
    float f2 = r * (1.0f / 15.0f);          // SIGMA_RGB = 15
    float f3 = g * (1.0f / 15.0f);
    float f4 = b * (1.0f / 15.0f);
    float h = -0.5f * LOG2E * (f0*f0 + f1*f1 + f2*f2 + f3*f3 + f4*f4);

    const float* sb = seg + (size_t)n * 2 * 16384;
    float s0 = 0.25f * (sb[o] + sb[o+1] + sb[o+128] + sb[o+129]);

    f[0] = f0 * SQ; f[1] = f1 * SQ; f[2] = f2 * SQ; f[3] = f3 * SQ; f[4] = f4 * SQ;
    f[5] = h;       f[6] = s0;
}

// ---------------------------------------------------------------------------
// block = (image n, upper-tri tile (i,j)). One p per thread (registers,
// components broadcast {c,c}); q-tile in smem as f32x2 over q-pairs.
// ---------------------------------------------------------------------------
__global__ void __launch_bounds__(THREADS)
crf_main(const float* __restrict__ img, const float* __restrict__ seg,
         float* __restrict__ out) {
    __shared__ u64 sq[(TS / 2) * 8];   // 256 q-pairs x 8 packed comps = 16KB

    int blk = blockIdx.x;
    int n = blk / NTRI;
    int t = blk % NTRI;
    int i = 0;
    {
        int rem = t;
        while (rem >= NT - i) { rem -= NT - i; i++; }
        t = i + rem;   // j
    }
    int j = t;
    int tid = threadIdx.x;

    // q-tile -> smem, packed-pair layout: [f0,f1,f2,f3,f4,h,s0,pad] x2 lanes.
    {
        float f[7];
        feat(img, seg, n, j * TS + tid, f);
        int pr = tid >> 1, half = tid & 1;
        float* s = reinterpret_cast<float*>(&sq[pr * 8]);
        #pragma unroll
        for (int c = 0; c < 7; c++) s[c * 2 + half] = f[c];
    }

    // p features in registers, broadcast-packed {c,c}.
    u64 px0, px1, px2, px3, px4, hp, ap, bp, acc;
    {
        float f[7];
        feat(img, seg, n, i * TS + tid, f);
        px0 = pack2(f[0], f[0]); px1 = pack2(f[1], f[1]); px2 = pack2(f[2], f[2]);
        px3 = pack2(f[3], f[3]); px4 = pack2(f[4], f[4]);
        hp = pack2(f[5], f[5]);
        float a = 2.0f * f[6] - 1.0f, b = 1.0f - f[6];
        ap = pack2(a, a);
        bp = pack2(b, b);
        acc = pack2(0.0f, 0.0f);
    }
    __syncthreads();

    #pragma unroll 4
    for (int jq = 0; jq < TS / 2; jq++) {
        const ulonglong2* qd = reinterpret_cast<const ulonglong2*>(&sq[jq * 8]);
        ulonglong2 A = qd[0];   // {f0 pair, f1 pair}
        ulonglong2 B = qd[1];   // {f2 pair, f3 pair}
        ulonglong2 C = qd[2];   // {f4 pair, h  pair}
        ulonglong2 D = qd[3];   // {s0 pair, pad}
        u64 L = add2(hp, C.y);
        L = fma2(px0, A.x, L);
        L = fma2(px1, A.y, L);
        L = fma2(px2, B.x, L);
        L = fma2(px3, B.y, L);
        L = fma2(px4, C.x, L);
        float2 Lf = unpack2(L);
        u64 k2 = pack2(ex2f(Lf.x), ex2f(Lf.y));
        u64 w = fma2(D.x, ap, bp);          // s0q*(2*s0p-1) + (1-s0p)
        acc = fma2(k2, w, acc);
    }

    float2 av = unpack2(acc);
    float a = av.x + av.y;
    if (i != j) a *= 2.0f;   // symmetry weight

    // Deterministic block reduction.
    __shared__ float red[THREADS / 32];
    #pragma unroll
    for (int o = 16; o; o >>= 1) a += __shfl_down_sync(0xffffffffu, a, o);
    if ((tid & 31) == 0) red[tid >> 5] = a;
    __syncthreads();
    __shared__ bool is_last;
    if (tid == 0) {
        float v = 0.0f;
        #pragma unroll
        for (int w = 0; w < THREADS / 32; w++) v += red[w];
        g_partial[blk] = v;
        __threadfence();
        unsigned int c = atomicAdd(&g_count, 1u);
        is_last = (c == NBLOCKS - 1);
    }
    __syncthreads();

    // Last block: deterministic fixed-order final reduction + counter reset.
    if (is_last) {
        __threadfence();
        if (tid < 32) {
            float v = 0.0f;
            // fixed index order: lane L sums partials L, L+32, L+64, ... then tree
            for (int k = tid; k < NBLOCKS; k += 32) v += g_partial[k];
            #pragma unroll
            for (int o = 16; o; o >>= 1) v += __shfl_down_sync(0xffffffffu, v, o);
            if (tid == 0) {
                out[0] = -(2e-9f / (float)N_IMG) * v;   // WEIGHT * (-sum / N)
                g_count = 0;                             // reset for next replay
            }
        }
    }
}

extern "C" void kernel_launch(void* const* d_in, const int* in_sizes, int n_in,
                              void* d_out, int out_size) {
    const float* images = (const float*)d_in[0];
    const float* segs   = (const float*)d_in[1];
    float* out = (float*)d_out;
    crf_main<<<NBLOCKS, THREADS>>>(images, segs, out);
}

// round 9
// speedup vs baseline: 1.2610x; 1.2610x over previous
#include <cuda_runtime.h>

// DenseCRFLoss on GB300 — R5: fine tiles (TS=256) for ~4 blocks/SM occupancy,
// TP=2 smem amortization, s0+s1=1 identity, fused counter-based finalize.
//
// loss = -(1/N) * sum_{n,k,p,q} S[n,k,p] * exp(-0.5*||f_p - f_q||^2) * S[n,k,q]
// out  = WEIGHT * loss, WEIGHT = 2e-9, N = 4.
// Exponent in log2 units: K_pq = exp2( f'_p . f'_q + h'_p + h'_q ).
// Symmetry: total = sum(diag tiles) + 2*sum(strict-upper tiles).
// Class identity (s0+s1=1): w = s0q*(2*s0p-1) + (1-s0p).

#define N_IMG   4
#define P       4096
#define TS      256             // square tile size
#define NT      16              // P / TS
#define NTRI    136             // NT*(NT+1)/2
#define NBLOCKS (N_IMG * NTRI)  // 544
#define THREADS 128
#define TP      2               // p's per thread (THREADS*TP == TS)

typedef unsigned long long u64;

__device__ float g_partial[NBLOCKS];
__device__ unsigned int g_count;   // zero-init; reset by last block each run

__device__ __forceinline__ float ex2f(float x) {
    float r; asm("ex2.approx.f32 %0, %1;" : "=f"(r) : "f"(x)); return r;
}
__device__ __forceinline__ u64 fma2(u64 a, u64 b, u64 c) {
    u64 d; asm("fma.rn.f32x2 %0, %1, %2, %3;" : "=l"(d) : "l"(a), "l"(b), "l"(c)); return d;
}
__device__ __forceinline__ u64 add2(u64 a, u64 b) {
    u64 d; asm("add.rn.f32x2 %0, %1, %2;" : "=l"(d) : "l"(a), "l"(b)); return d;
}
__device__ __forceinline__ u64 pack2(float lo, float hi) {
    u64 d; asm("mov.b64 %0, {%1, %2};" : "=l"(d) : "f"(lo), "f"(hi)); return d;
}
__device__ __forceinline__ float2 unpack2(u64 v) {
    float2 r; asm("mov.b64 {%0, %1}, %2;" : "=f"(r.x), "=f"(r.y) : "l"(v)); return r;
}

// Feature record: f[0..4] = feature * sqrt(log2e), f[5] = -0.5*log2e*|f|^2, f[6] = s0.
__device__ __forceinline__ void feat(const float* __restrict__ img,
                                     const float* __restrict__ seg,
                                     int n, int pix, float f[7]) {
    const float LOG2E = 1.44269504088896340736f;
    const float SQ    = 1.20112240878644981f;   // sqrt(LOG2E)
    int y = pix >> 6, x = pix & 63;
    int o = (2 * y) * 128 + 2 * x;

    const float* ib = img + (size_t)n * 3 * 16384;
    float r = ib[o];
    float g = ib[16384 + o];
    float b = ib[32768 + o];

    float f0 = (float)x * (1.0f / 50.0f);   // SIGMA_XY * SCALE = 50
    float f1 = (float)y * (1.0f / 50.0f);
    float f2 = r * (1.0f / 15.0f);          // SIGMA_RGB = 15
    float f3 = g * (1.0f / 15.0f);
    float f4 = b * (1.0f / 15.0f);
    float h = -0.5f * LOG2E * (f0*f0 + f1*f1 + f2*f2 + f3*f3 + f4*f4);

    const float* sb = seg + (size_t)n * 2 * 16384;
    float s0 = 0.25f * (sb[o] + sb[o+1] + sb[o+128] + sb[o+129]);

    f[0] = f0 * SQ; f[1] = f1 * SQ; f[2] = f2 * SQ; f[3] = f3 * SQ; f[4] = f4 * SQ;
    f[5] = h;       f[6] = s0;
}

// ---------------------------------------------------------------------------
// block = (image n, upper-tri tile (i,j) of the 16x16 tile grid).
// TP=2 p's per thread in registers (components broadcast {c,c});
// q-tile in smem packed as f32x2 over consecutive q-pairs.
// ---------------------------------------------------------------------------
__global__ void __launch_bounds__(THREADS)
crf_main(const float* __restrict__ img, const float* __restrict__ seg,
         float* __restrict__ out) {
    __shared__ u64 sq[(TS / 2) * 8];   // 128 q-pairs x 8 packed comps = 8KB

    int blk = blockIdx.x;
    int n = blk / NTRI;
    int t = blk % NTRI;
    int i = 0;
    {
        int rem = t;
        while (rem >= NT - i) { rem -= NT - i; i++; }
        t = i + rem;   // j
    }
    int j = t;
    int tid = threadIdx.x;

    // q-tile -> smem, packed-pair layout: [f0,f1,f2,f3,f4,h,s0,pad] x2 lanes.
    #pragma unroll
    for (int k = 0; k < TS / THREADS; k++) {
        int qk = tid + k * THREADS;
        float f[7];
        feat(img, seg, n, j * TS + qk, f);
        int pr = qk >> 1, half = qk & 1;
        float* s = reinterpret_cast<float*>(&sq[pr * 8]);
        #pragma unroll
        for (int c = 0; c < 7; c++) s[c * 2 + half] = f[c];
    }

    // p features in registers, broadcast-packed {c,c}.
    u64 px[TP][5], hp[TP], ap[TP], bp[TP], acc[TP];
    #pragma unroll
    for (int tp = 0; tp < TP; tp++) {
        float f[7];
        feat(img, seg, n, i * TS + tid + tp * THREADS, f);
        #pragma unroll
        for (int c = 0; c < 5; c++) px[tp][c] = pack2(f[c], f[c]);
        hp[tp] = pack2(f[5], f[5]);
        float av = 2.0f * f[6] - 1.0f, bv = 1.0f - f[6];
        ap[tp] = pack2(av, av);
        bp[tp] = pack2(bv, bv);
        acc[tp] = pack2(0.0f, 0.0f);
    }
    __syncthreads();

    #pragma unroll 4
    for (int jq = 0; jq < TS / 2; jq++) {
        const ulonglong2* qd = reinterpret_cast<const ulonglong2*>(&sq[jq * 8]);
        ulonglong2 A = qd[0];   // {f0 pair, f1 pair}
        ulonglong2 B = qd[1];   // {f2 pair, f3 pair}
        ulonglong2 C = qd[2];   // {f4 pair, h  pair}
        ulonglong2 D = qd[3];   // {s0 pair, pad}
        #pragma unroll
        for (int tp = 0; tp < TP; tp++) {
            u64 L = add2(hp[tp], C.y);
            L = fma2(px[tp][0], A.x, L);
            L = fma2(px[tp][1], A.y, L);
            L = fma2(px[tp][2], B.x, L);
            L = fma2(px[tp][3], B.y, L);
            L = fma2(px[tp][4], C.x, L);
            float2 Lf = unpack2(L);
            u64 k2 = pack2(ex2f(Lf.x), ex2f(Lf.y));
            u64 w = fma2(D.x, ap[tp], bp[tp]);   // s0q*(2*s0p-1) + (1-s0p)
            acc[tp] = fma2(k2, w, acc[tp]);
        }
    }

    float a = 0.0f;
    #pragma unroll
    for (int tp = 0; tp < TP; tp++) {
        float2 av = unpack2(acc[tp]);
        a += av.x + av.y;
    }
    if (i != j) a *= 2.0f;   // symmetry weight

    // Deterministic block reduction.
    __shared__ float red[THREADS / 32];
    #pragma unroll
    for (int o = 16; o; o >>= 1) a += __shfl_down_sync(0xffffffffu, a, o);
    if ((tid & 31) == 0) red[tid >> 5] = a;
    __syncthreads();
    __shared__ bool is_last;
    if (tid == 0) {
        float v = 0.0f;
        #pragma unroll
        for (int w = 0; w < THREADS / 32; w++) v += red[w];
        g_partial[blk] = v;
        __threadfence();
        unsigned int c = atomicAdd(&g_count, 1u);
        is_last = (c == NBLOCKS - 1);
    }
    __syncthreads();

    // Last block: deterministic fixed-order final reduction + counter reset.
    if (is_last) {
        __threadfence();
        if (tid < 32) {
            float v = 0.0f;
            for (int k = tid; k < NBLOCKS; k += 32) v += g_partial[k];
            #pragma unroll
            for (int o = 16; o; o >>= 1) v += __shfl_down_sync(0xffffffffu, v, o);
            if (tid == 0) {
                out[0] = -(2e-9f / (float)N_IMG) * v;   // WEIGHT * (-sum / N)
                g_count = 0;                             // reset for next replay
            }
        }
    }
}

extern "C" void kernel_launch(void* const* d_in, const int* in_sizes, int n_in,
                              void* d_out, int out_size) {
    const float* images = (const float*)d_in[0];
    const float* segs   = (const float*)d_in[1];
    float* out = (float*)d_out;
    crf_main<<<NBLOCKS, THREADS>>>(images, segs, out);
}

// round 12
// speedup vs baseline: 1.3377x; 1.0608x over previous
#include <cuda_runtime.h>

// DenseCRFLoss on GB300 — R6: R3 block shape (256 thr, TP=2, p-tile 512) with
// q-split x4 for ~31 warps/SM occupancy; s0+s1=1 identity; fused finalize.
//
// loss = -(1/N) * sum_{n,k,p,q} S[n,k,p] * exp(-0.5*||f_p - f_q||^2) * S[n,k,q]
// out  = WEIGHT * loss, WEIGHT = 2e-9, N = 4.
// Exponent in log2 units: K_pq = exp2( f'_p . f'_q + h'_p + h'_q ).
// Symmetry: total = sum(diag tiles) + 2*sum(strict-upper tiles).
// Class identity (s0+s1=1): w = s0q*(2*s0p-1) + (1-s0p).

#define N_IMG   4
#define P       4096
#define TS      512             // square tile size (p side)
#define NT      8               // P / TS
#define NTRI    36              // upper-tri tiles
#define QSPLIT  4               // q-chunks per tile
#define QC      (TS / QSPLIT)   // 128 q's per block
#define NBLOCKS (N_IMG * NTRI * QSPLIT)  // 576
#define THREADS 256
#define TP      2               // p's per thread (THREADS*TP == TS)

typedef unsigned long long u64;

__device__ float g_partial[NBLOCKS];
__device__ unsigned int g_count;   // zero-init; reset by last block each run

__device__ __forceinline__ float ex2f(float x) {
    float r; asm("ex2.approx.f32 %0, %1;" : "=f"(r) : "f"(x)); return r;
}
__device__ __forceinline__ u64 fma2(u64 a, u64 b, u64 c) {
    u64 d; asm("fma.rn.f32x2 %0, %1, %2, %3;" : "=l"(d) : "l"(a), "l"(b), "l"(c)); return d;
}
__device__ __forceinline__ u64 add2(u64 a, u64 b) {
    u64 d; asm("add.rn.f32x2 %0, %1, %2;" : "=l"(d) : "l"(a), "l"(b)); return d;
}
__device__ __forceinline__ u64 pack2(float lo, float hi) {
    u64 d; asm("mov.b64 %0, {%1, %2};" : "=l"(d) : "f"(lo), "f"(hi)); return d;
}
__device__ __forceinline__ float2 unpack2(u64 v) {
    float2 r; asm("mov.b64 {%0, %1}, %2;" : "=f"(r.x), "=f"(r.y) : "l"(v)); return r;
}

// Feature record: f[0..4] = feature * sqrt(log2e), f[5] = -0.5*log2e*|f|^2, f[6] = s0.
__device__ __forceinline__ void feat(const float* __restrict__ img,
                                     const float* __restrict__ seg,
                                     int n, int pix, float f[7]) {
    const float LOG2E = 1.44269504088896340736f;
    const float SQ    = 1.20112240878644981f;   // sqrt(LOG2E)
    int y = pix >> 6, x = pix & 63;
    int o = (2 * y) * 128 + 2 * x;

    const float* ib = img + (size_t)n * 3 * 16384;
    float r = ib[o];
    float g = ib[16384 + o];
    float b = ib[32768 + o];

    float f0 = (float)x * (1.0f / 50.0f);   // SIGMA_XY * SCALE = 50
    float f1 = (float)y * (1.0f / 50.0f);
    float f2 = r * (1.0f / 15.0f);          // SIGMA_RGB = 15
    float f3 = g * (1.0f / 15.0f);
    float f4 = b * (1.0f / 15.0f);
    float h = -0.5f * LOG2E * (f0*f0 + f1*f1 + f2*f2 + f3*f3 + f4*f4);

    const float* sb = seg + (size_t)n * 2 * 16384;
    float s0 = 0.25f * (sb[o] + sb[o+1] + sb[o+128] + sb[o+129]);

    f[0] = f0 * SQ; f[1] = f1 * SQ; f[2] = f2 * SQ; f[3] = f3 * SQ; f[4] = f4 * SQ;
    f[5] = h;       f[6] = s0;
}

// ---------------------------------------------------------------------------
// block = (image n, upper-tri tile (i,j), q-chunk qc). p-tile i (512) in
// registers, q-chunk (128 of tile j) in smem packed as f32x2 over q-pairs.
// ---------------------------------------------------------------------------
__global__ void __launch_bounds__(THREADS)
crf_main(const float* __restrict__ img, const float* __restrict__ seg,
         float* __restrict__ out) {
    __shared__ u64 sq[(QC / 2) * 8];   // 64 q-pairs x 8 packed comps = 4KB

    int blk = blockIdx.x;
    int qc = blk & (QSPLIT - 1);
    int t  = (blk >> 2) % NTRI;
    int n  = blk / (NTRI * QSPLIT);
    int i = 0;
    {
        int rem = t;
        while (rem >= NT - i) { rem -= NT - i; i++; }
        t = i + rem;   // j
    }
    int j = t;
    int tid = threadIdx.x;

    // q-chunk -> smem (128 q's, threads 0..127), packed-pair layout.
    if (tid < QC) {
        float f[7];
        feat(img, seg, n, j * TS + qc * QC + tid, f);
        int pr = tid >> 1, half = tid & 1;
        float* s = reinterpret_cast<float*>(&sq[pr * 8]);
        #pragma unroll
        for (int c = 0; c < 7; c++) s[c * 2 + half] = f[c];
    }

    // p features in registers, broadcast-packed {c,c}.
    u64 px[TP][5], hp[TP], ap[TP], bp[TP], acc[TP];
    #pragma unroll
    for (int tp = 0; tp < TP; tp++) {
        float f[7];
        feat(img, seg, n, i * TS + tid + tp * THREADS, f);
        #pragma unroll
        for (int c = 0; c < 5; c++) px[tp][c] = pack2(f[c], f[c]);
        hp[tp] = pack2(f[5], f[5]);
        float av = 2.0f * f[6] - 1.0f, bv = 1.0f - f[6];
        ap[tp] = pack2(av, av);
        bp[tp] = pack2(bv, bv);
        acc[tp] = pack2(0.0f, 0.0f);
    }
    __syncthreads();

    #pragma unroll 4
    for (int jq = 0; jq < QC / 2; jq++) {
        const ulonglong2* qd = reinterpret_cast<const ulonglong2*>(&sq[jq * 8]);
        ulonglong2 A = qd[0];   // {f0 pair, f1 pair}
        ulonglong2 B = qd[1];   // {f2 pair, f3 pair}
        ulonglong2 C = qd[2];   // {f4 pair, h  pair}
        ulonglong2 D = qd[3];   // {s0 pair, pad}
        #pragma unroll
        for (int tp = 0; tp < TP; tp++) {
            u64 L = add2(hp[tp], C.y);
            L = fma2(px[tp][0], A.x, L);
            L = fma2(px[tp][1], A.y, L);
            L = fma2(px[tp][2], B.x, L);
            L = fma2(px[tp][3], B.y, L);
            L = fma2(px[tp][4], C.x, L);
            float2 Lf = unpack2(L);
            u64 k2 = pack2(ex2f(Lf.x), ex2f(Lf.y));
            u64 w = fma2(D.x, ap[tp], bp[tp]);   // s0q*(2*s0p-1) + (1-s0p)
            acc[tp] = fma2(k2, w, acc[tp]);
        }
    }

    float a = 0.0f;
    #pragma unroll
    for (int tp = 0; tp < TP; tp++) {
        float2 av = unpack2(acc[tp]);
        a += av.x + av.y;
    }
    if (i != j) a *= 2.0f;   // symmetry weight

    // Deterministic block reduction.
    __shared__ float red[THREADS / 32];
    #pragma unroll
    for (int o = 16; o; o >>= 1) a += __shfl_down_sync(0xffffffffu, a, o);
    if ((tid & 31) == 0) red[tid >> 5] = a;
    __syncthreads();
    __shared__ bool is_last;
    if (tid == 0) {
        float v = 0.0f;
        #pragma unroll
        for (int w = 0; w < THREADS / 32; w++) v += red[w];
        g_partial[blk] = v;
        __threadfence();
        unsigned int c = atomicAdd(&g_count, 1u);
        is_last = (c == NBLOCKS - 1);
    }
    __syncthreads();

    // Last block: deterministic fixed-order final reduction + counter reset.
    if (is_last) {
        __threadfence();
        if (tid < 32) {
            float v = 0.0f;
            for (int k = tid; k < NBLOCKS; k += 32) v += g_partial[k];
            #pragma unroll
            for (int o = 16; o; o >>= 1) v += __shfl_down_sync(0xffffffffu, v, o);
            if (tid == 0) {
                out[0] = -(2e-9f / (float)N_IMG) * v;   // WEIGHT * (-sum / N)
                g_count = 0;                             // reset for next replay
            }
        }
    }
}

extern "C" void kernel_launch(void* const* d_in, const int* in_sizes, int n_in,
                              void* d_out, int out_size) {
    const float* images = (const float*)d_in[0];
    const float* segs   = (const float*)d_in[1];
    float* out = (float*)d_out;
    crf_main<<<NBLOCKS, THREADS>>>(images, segs, out);
}

// round 13
// speedup vs baseline: 1.5714x; 1.1747x over previous
#include <cuda_runtime.h>

// DenseCRFLoss on GB300 — R7: precomputed feature records, split accumulators,
// fully unrolled mainloop, QSPLIT=8 for ~40 warps/SM.
//
// loss = -(1/N) * sum_{n,k,p,q} S[n,k,p] * exp(-0.5*||f_p - f_q||^2) * S[n,k,q]
// out  = WEIGHT * loss, WEIGHT = 2e-9, N = 4.
// K_pq = exp2( f'_p . f'_q + h'_p + h'_q ), f' = f*sqrt(log2e), h' = -0.5*log2e*|f|^2.
// Symmetry: total = sum(diag tiles) + 2*sum(strict-upper tiles).
// s0+s1=1: w = s0q*(2*s0p-1) + (1-s0p) = a_p*s0q + b_p -> split accumulators.

#define N_IMG   4
#define P       4096
#define TS      512             // tile side
#define NT      8               // P / TS
#define NTRI    36              // upper-tri tiles
#define QSPLIT  8               // q-chunks per tile
#define QC      (TS / QSPLIT)   // 64 q's per block
#define NBLOCKS (N_IMG * NTRI * QSPLIT)  // 1152
#define THREADS 256
#define TP      2               // p's per thread (THREADS*TP == TS)

typedef unsigned long long u64;

__device__ u64   g_qrec[N_IMG * (P / 2) * 8];   // packed-pair records, 64B each
__device__ float g_pfeat[N_IMG * P * 8];        // per-pixel [f0..f4, h, a, b]
__device__ float g_partial[NBLOCKS];
__device__ unsigned int g_count;                // zero-init; reset each run

__device__ __forceinline__ float ex2f(float x) {
    float r; asm("ex2.approx.f32 %0, %1;" : "=f"(r) : "f"(x)); return r;
}
__device__ __forceinline__ u64 fma2(u64 a, u64 b, u64 c) {
    u64 d; asm("fma.rn.f32x2 %0, %1, %2, %3;" : "=l"(d) : "l"(a), "l"(b), "l"(c)); return d;
}
__device__ __forceinline__ u64 add2(u64 a, u64 b) {
    u64 d; asm("add.rn.f32x2 %0, %1, %2;" : "=l"(d) : "l"(a), "l"(b)); return d;
}
__device__ __forceinline__ u64 pack2(float lo, float hi) {
    u64 d; asm("mov.b64 %0, {%1, %2};" : "=l"(d) : "f"(lo), "f"(hi)); return d;
}
__device__ __forceinline__ float2 unpack2(u64 v) {
    float2 r; asm("mov.b64 {%0, %1}, %2;" : "=f"(r.x), "=f"(r.y) : "l"(v)); return r;
}

// Feature for pixel pix of image n: f[0..4] scaled features, f[5]=h', f[6]=s0.
__device__ __forceinline__ void feat(const float* __restrict__ img,
                                     const float* __restrict__ seg,
                                     int n, int pix, float f[7]) {
    const float LOG2E = 1.44269504088896340736f;
    const float SQ    = 1.20112240878644981f;   // sqrt(LOG2E)
    int y = pix >> 6, x = pix & 63;
    int o = (2 * y) * 128 + 2 * x;

    const float* ib = img + (size_t)n * 3 * 16384;
    float r = ib[o];
    float g = ib[16384 + o];
    float b = ib[32768 + o];

    float f0 = (float)x * (1.0f / 50.0f);   // SIGMA_XY * SCALE = 50
    float f1 = (float)y * (1.0f / 50.0f);
    float f2 = r * (1.0f / 15.0f);          // SIGMA_RGB = 15
    float f3 = g * (1.0f / 15.0f);
    float f4 = b * (1.0f / 15.0f);
    float h = -0.5f * LOG2E * (f0*f0 + f1*f1 + f2*f2 + f3*f3 + f4*f4);

    const float* sb = seg + (size_t)n * 2 * 16384;
    float s0 = 0.25f * (sb[o] + sb[o+1] + sb[o+128] + sb[o+129]);

    f[0] = f0 * SQ; f[1] = f1 * SQ; f[2] = f2 * SQ; f[3] = f3 * SQ; f[4] = f4 * SQ;
    f[5] = h;       f[6] = s0;
}

// ---------------------------------------------------------------------------
// Prep: one thread per pixel-PAIR. Writes the packed-pair q-record and both
// per-pixel p-records.
// ---------------------------------------------------------------------------
__global__ void __launch_bounds__(256)
crf_prep(const float* __restrict__ img, const float* __restrict__ seg) {
    int pr = blockIdx.x * blockDim.x + threadIdx.x;   // record index
    if (pr >= N_IMG * (P / 2)) return;
    int n = pr / (P / 2);
    int r = pr % (P / 2);

    float fA[7], fB[7];
    feat(img, seg, n, 2 * r,     fA);
    feat(img, seg, n, 2 * r + 1, fB);

    float4* q = reinterpret_cast<float4*>(&g_qrec[(size_t)pr * 8]);
    q[0] = make_float4(fA[0], fB[0], fA[1], fB[1]);
    q[1] = make_float4(fA[2], fB[2], fA[3], fB[3]);
    q[2] = make_float4(fA[4], fB[4], fA[5], fB[5]);
    q[3] = make_float4(fA[6], fB[6], 0.0f, 0.0f);

    float4* pA = reinterpret_cast<float4*>(&g_pfeat[(size_t)(2 * pr) * 8]);
    pA[0] = make_float4(fA[0], fA[1], fA[2], fA[3]);
    pA[1] = make_float4(fA[4], fA[5], 2.0f * fA[6] - 1.0f, 1.0f - fA[6]);
    float4* pB = reinterpret_cast<float4*>(&g_pfeat[(size_t)(2 * pr + 1) * 8]);
    pB[0] = make_float4(fB[0], fB[1], fB[2], fB[3]);
    pB[1] = make_float4(fB[4], fB[5], 2.0f * fB[6] - 1.0f, 1.0f - fB[6]);
}

// ---------------------------------------------------------------------------
// Main: block = (image n, tri-tile (i,j), q-chunk qc). p-tile (512) in regs,
// q-chunk (64 q = 32 records = 2KB) in smem.
// ---------------------------------------------------------------------------
__global__ void __launch_bounds__(THREADS)
crf_main(float* __restrict__ out) {
    __shared__ u64 sq[(QC / 2) * 8];   // 32 records x 64B = 2KB

    int blk = blockIdx.x;
    int qc = blk & (QSPLIT - 1);
    int t  = (blk >> 3) % NTRI;
    int n  = blk / (NTRI * QSPLIT);
    int i = 0;
    {
        int rem = t;
        while (rem >= NT - i) { rem -= NT - i; i++; }
        t = i + rem;   // j
    }
    int j = t;
    int tid = threadIdx.x;

    // q-chunk copy: 32 records = 256 u64; one u64 per thread.
    {
        const u64* src = &g_qrec[(size_t)(n * (P / 2) + j * (TS / 2) + qc * (QC / 2)) * 8];
        sq[tid] = src[tid];
    }

    // p records -> broadcast-packed registers.
    u64 px[TP][5], hp[TP], acc0[TP], acc1[TP];
    float ap[TP], bp[TP];
    #pragma unroll
    for (int tp = 0; tp < TP; tp++) {
        const float4* pf = reinterpret_cast<const float4*>(
            &g_pfeat[(size_t)(n * P + i * TS + tid + tp * THREADS) * 8]);
        float4 v0 = pf[0];
        float4 v1 = pf[1];
        px[tp][0] = pack2(v0.x, v0.x);
        px[tp][1] = pack2(v0.y, v0.y);
        px[tp][2] = pack2(v0.z, v0.z);
        px[tp][3] = pack2(v0.w, v0.w);
        px[tp][4] = pack2(v1.x, v1.x);
        hp[tp]    = pack2(v1.y, v1.y);
        ap[tp] = v1.z;
        bp[tp] = v1.w;
        acc0[tp] = 0ull;
        acc1[tp] = 0ull;
    }
    __syncthreads();

    #pragma unroll
    for (int jq = 0; jq < QC / 2; jq++) {
        const ulonglong2* qd = reinterpret_cast<const ulonglong2*>(&sq[jq * 8]);
        ulonglong2 A = qd[0];   // {f0 pair, f1 pair}
        ulonglong2 B = qd[1];   // {f2 pair, f3 pair}
        ulonglong2 C = qd[2];   // {f4 pair, h  pair}
        ulonglong2 D = qd[3];   // {s0 pair, pad}
        #pragma unroll
        for (int tp = 0; tp < TP; tp++) {
            u64 L = add2(hp[tp], C.y);
            L = fma2(px[tp][0], A.x, L);
            L = fma2(px[tp][1], A.y, L);
            L = fma2(px[tp][2], B.x, L);
            L = fma2(px[tp][3], B.y, L);
            L = fma2(px[tp][4], C.x, L);
            float2 Lf = unpack2(L);
            u64 k2 = pack2(ex2f(Lf.x), ex2f(Lf.y));
            acc1[tp] = fma2(k2, D.x, acc1[tp]);   // sum k * s0q
            acc0[tp] = add2(k2, acc0[tp]);        // sum k
        }
    }

    float a = 0.0f;
    #pragma unroll
    for (int tp = 0; tp < TP; tp++) {
        float2 a1 = unpack2(acc1[tp]);
        float2 a0 = unpack2(acc0[tp]);
        a += ap[tp] * (a1.x + a1.y) + bp[tp] * (a0.x + a0.y);
    }
    if (i != j) a *= 2.0f;   // symmetry weight

    // Deterministic block reduction.
    __shared__ float red[THREADS / 32];
    #pragma unroll
    for (int o = 16; o; o >>= 1) a += __shfl_down_sync(0xffffffffu, a, o);
    if ((tid & 31) == 0) red[tid >> 5] = a;
    __syncthreads();
    __shared__ bool is_last;
    if (tid == 0) {
        float v = 0.0f;
        #pragma unroll
        for (int w = 0; w < THREADS / 32; w++) v += red[w];
        g_partial[blk] = v;
        __threadfence();
        unsigned int c = atomicAdd(&g_count, 1u);
        is_last = (c == NBLOCKS - 1);
    }
    __syncthreads();

    // Last block: deterministic fixed-order final reduction + counter reset.
    if (is_last) {
        __threadfence();
        if (tid < 32) {
            float v = 0.0f;
            for (int k = tid; k < NBLOCKS; k += 32) v += g_partial[k];
            #pragma unroll
            for (int o = 16; o; o >>= 1) v += __shfl_down_sync(0xffffffffu, v, o);
            if (tid == 0) {
                out[0] = -(2e-9f / (float)N_IMG) * v;   // WEIGHT * (-sum / N)
                g_count = 0;                             // reset for next replay
            }
        }
    }
}

extern "C" void kernel_launch(void* const* d_in, const int* in_sizes, int n_in,
                              void* d_out, int out_size) {
    const float* images = (const float*)d_in[0];
    const float* segs   = (const float*)d_in[1];
    float* out = (float*)d_out;

    crf_prep<<<(N_IMG * (P / 2) + 255) / 256, 256>>>(images, segs);
    crf_main<<<NBLOCKS, THREADS>>>(out);
}